// round 6
// baseline (speedup 1.0000x reference)
#include <cuda_runtime.h>

#define LN_EPS 1e-5f

// 4 lanes per row, 8 rows per warp, 8 warps/block => 64 rows/block.
// Each thread front-batches 8x LDG.128 from its row (MLP=8), local-reduces
// 32 elements, then a 2-step shuffle reduction within its 4-lane group.
__global__ void __launch_bounds__(256) typenorm_kernel(
    const int*    __restrict__ types,   // type_list (int32 view)
    const float4* __restrict__ x,       // [N, 32] float4 view of [N,128] f32
    const float4* __restrict__ gamma,   // [T, 32]
    const float4* __restrict__ beta,    // [T, 32]
    float4*       __restrict__ out,     // [N, 32]
    int n_rows)
{
    const int warp = threadIdx.x >> 5;
    const int lane = threadIdx.x & 31;
    const int sub  = lane & 3;          // position within row (4 lanes/row)
    const int r    = lane >> 2;         // which of the warp's 8 rows

    const int row = (blockIdx.x << 6) + (warp << 3) + r;
    if (row >= n_rows) return;

    const float4* xr = x + row * 32;

    // Front-batched independent streaming loads: MLP=8 per thread.
    float4 v[8];
    #pragma unroll
    for (int i = 0; i < 8; i++)
        v[i] = __ldcs(&xr[sub + 4 * i]);

    // Local accumulation over 32 elements.
    float s = 0.f, ss = 0.f;
    #pragma unroll
    for (int i = 0; i < 8; i++) {
        s  += ((v[i].x + v[i].y) + (v[i].z + v[i].w));
        ss += v[i].x * v[i].x + v[i].y * v[i].y
            + v[i].z * v[i].z + v[i].w * v[i].w;
    }

    // Cross-lane reduction within aligned 4-lane group: 2 steps.
    #pragma unroll
    for (int off = 2; off > 0; off >>= 1) {
        s  += __shfl_xor_sync(0xFFFFFFFFu, s,  off);
        ss += __shfl_xor_sync(0xFFFFFFFFu, ss, off);
    }

    const float inv_d = 1.0f / 128.0f;
    const float mean  = s * inv_d;
    const float var   = fmaf(ss, inv_d, -mean * mean);  // biased variance
    const float rstd  = rsqrtf(var + LN_EPS);

    // Type-indexed affine params: 4 KB tables, L1/L2 resident.
    const int t = __ldg(&types[row]);
    const float4* gr = gamma + t * 32;
    const float4* br = beta  + t * 32;

    float4* outr = out + row * 32;

    #pragma unroll
    for (int i = 0; i < 8; i++) {
        const float4 g = __ldg(&gr[sub + 4 * i]);
        const float4 b = __ldg(&br[sub + 4 * i]);
        float4 o;
        o.x = fmaf((v[i].x - mean) * rstd, g.x, b.x);
        o.y = fmaf((v[i].y - mean) * rstd, g.y, b.y);
        o.z = fmaf((v[i].z - mean) * rstd, g.z, b.z);
        o.w = fmaf((v[i].w - mean) * rstd, g.w, b.w);
        __stcs(&outr[sub + 4 * i], o);
    }
}

extern "C" void kernel_launch(void* const* d_in, const int* in_sizes, int n_in,
                              void* d_out, int out_size)
{
    const int*    types = (const int*)   d_in[0];
    const float4* x     = (const float4*)d_in[1];
    const float4* gamma = (const float4*)d_in[2];
    const float4* beta  = (const float4*)d_in[3];
    float4*       out   = (float4*)      d_out;

    const int n_rows = in_sizes[1] / 128;

    const int rows_per_block = 64;
    const int blocks = (n_rows + rows_per_block - 1) / rows_per_block;
    typenorm_kernel<<<blocks, 256>>>(types, x, gamma, beta, out, n_rows);
}